// round 1
// baseline (speedup 1.0000x reference)
#include <cuda_runtime.h>
#include <math_constants.h>

static constexpr int B = 8, S = 2048, D = 768;
static constexpr int M_TOT = B * S; // 16384

// Scratch (allocation-free rule: __device__ globals)
__device__ float g_Wx[(size_t)B * S * D]; // 48 MB
__device__ float g_s [(size_t)B * S * S]; // 134 MB
__device__ float g_c [(size_t)B * S * D]; // 48 MB

#define BM 128
#define BN 128
#define BK 8
#define TM 8
#define TN 8
#define NTHREADS 256

// ---------------------------------------------------------------------------
// C[M,N] = A[M,K] * B[N,K]^T   (both operands K-contiguous, "nt")
// Optional epilogue: C = resid + relu(C + bias)
// Batch via blockIdx.z with element strides sA/sB/sC.
// Requires M%BM==0, N%BN==0, K%BK==0 (true for all shapes here).
// ---------------------------------------------------------------------------
template <bool EPI>
__global__ __launch_bounds__(NTHREADS)
void gemm_nt_kernel(const float* __restrict__ A, const float* __restrict__ Bm,
                    float* __restrict__ C, int M, int N, int K,
                    size_t sA, size_t sB, size_t sC,
                    const float* __restrict__ bias,
                    const float* __restrict__ resid)
{
    __shared__ float As[BK][BM];
    __shared__ float Bs[BK][BN];

    const float* Ab = A  + (size_t)blockIdx.z * sA;
    const float* Bb = Bm + (size_t)blockIdx.z * sB;
    float*       Cb = C  + (size_t)blockIdx.z * sC;

    const int tid     = threadIdx.x;
    const int rowBase = blockIdx.y * BM;
    const int colBase = blockIdx.x * BN;
    const int tr = (tid / 16) * TM; // 0..120
    const int tc = (tid % 16) * TN; // 0..120

    // tile-load indices: 128 rows x 8 k  -> 256 float4
    const int lr  = tid >> 1;        // 0..127
    const int lk4 = (tid & 1) << 2;  // 0 or 4

    float acc[TM][TN] = {};

    for (int k0 = 0; k0 < K; k0 += BK) {
        float4 a4 = *(const float4*)(Ab + (size_t)(rowBase + lr) * K + k0 + lk4);
        float4 b4 = *(const float4*)(Bb + (size_t)(colBase + lr) * K + k0 + lk4);
        As[lk4 + 0][lr] = a4.x; As[lk4 + 1][lr] = a4.y;
        As[lk4 + 2][lr] = a4.z; As[lk4 + 3][lr] = a4.w;
        Bs[lk4 + 0][lr] = b4.x; Bs[lk4 + 1][lr] = b4.y;
        Bs[lk4 + 2][lr] = b4.z; Bs[lk4 + 3][lr] = b4.w;
        __syncthreads();
        #pragma unroll
        for (int k = 0; k < BK; ++k) {
            float af[TM], bf[TN];
            #pragma unroll
            for (int i = 0; i < TM; ++i) af[i] = As[k][tr + i];
            #pragma unroll
            for (int j = 0; j < TN; ++j) bf[j] = Bs[k][tc + j];
            #pragma unroll
            for (int i = 0; i < TM; ++i)
                #pragma unroll
                for (int j = 0; j < TN; ++j)
                    acc[i][j] = fmaf(af[i], bf[j], acc[i][j]);
        }
        __syncthreads();
    }

    #pragma unroll
    for (int i = 0; i < TM; ++i) {
        const size_t r = (size_t)(rowBase + tr + i);
        #pragma unroll
        for (int j = 0; j < TN; j += 4) {
            const size_t c = (size_t)(colBase + tc + j);
            float4 v = make_float4(acc[i][j], acc[i][j + 1], acc[i][j + 2], acc[i][j + 3]);
            if (EPI) {
                const float4 bb = *(const float4*)(bias + c);
                const float4 rr = *(const float4*)(resid + r * (size_t)N + c);
                v.x = fmaxf(v.x + bb.x, 0.f) + rr.x;
                v.y = fmaxf(v.y + bb.y, 0.f) + rr.y;
                v.z = fmaxf(v.z + bb.z, 0.f) + rr.z;
                v.w = fmaxf(v.w + bb.w, 0.f) + rr.w;
            }
            *(float4*)(Cb + r * (size_t)N + c) = v;
        }
    }
}

// ---------------------------------------------------------------------------
// C[M,N] = A[M,K] * B[K,N]   (A K-contiguous, B N-contiguous, "nn")
// ---------------------------------------------------------------------------
__global__ __launch_bounds__(NTHREADS)
void gemm_nn_kernel(const float* __restrict__ A, const float* __restrict__ Bm,
                    float* __restrict__ C, int M, int N, int K,
                    size_t sA, size_t sB, size_t sC)
{
    __shared__ float As[BK][BM];
    __shared__ float Bs[BK][BN];

    const float* Ab = A  + (size_t)blockIdx.z * sA;
    const float* Bb = Bm + (size_t)blockIdx.z * sB;
    float*       Cb = C  + (size_t)blockIdx.z * sC;

    const int tid     = threadIdx.x;
    const int rowBase = blockIdx.y * BM;
    const int colBase = blockIdx.x * BN;
    const int tr = (tid / 16) * TM;
    const int tc = (tid % 16) * TN;

    const int lr  = tid >> 1;
    const int lk4 = (tid & 1) << 2;
    const int bk  = tid >> 5;        // 0..7
    const int bn4 = (tid & 31) << 2; // 0..124

    float acc[TM][TN] = {};

    for (int k0 = 0; k0 < K; k0 += BK) {
        float4 a4 = *(const float4*)(Ab + (size_t)(rowBase + lr) * K + k0 + lk4);
        float4 b4 = *(const float4*)(Bb + (size_t)(k0 + bk) * N + colBase + bn4);
        As[lk4 + 0][lr] = a4.x; As[lk4 + 1][lr] = a4.y;
        As[lk4 + 2][lr] = a4.z; As[lk4 + 3][lr] = a4.w;
        *(float4*)&Bs[bk][bn4] = b4;
        __syncthreads();
        #pragma unroll
        for (int k = 0; k < BK; ++k) {
            float af[TM], bf[TN];
            #pragma unroll
            for (int i = 0; i < TM; ++i) af[i] = As[k][tr + i];
            #pragma unroll
            for (int j = 0; j < TN; ++j) bf[j] = Bs[k][tc + j];
            #pragma unroll
            for (int i = 0; i < TM; ++i)
                #pragma unroll
                for (int j = 0; j < TN; ++j)
                    acc[i][j] = fmaf(af[i], bf[j], acc[i][j]);
        }
        __syncthreads();
    }

    #pragma unroll
    for (int i = 0; i < TM; ++i) {
        const size_t r = (size_t)(rowBase + tr + i);
        #pragma unroll
        for (int j = 0; j < TN; j += 4) {
            const size_t c = (size_t)(colBase + tc + j);
            float4 v = make_float4(acc[i][j], acc[i][j + 1], acc[i][j + 2], acc[i][j + 3]);
            *(float4*)(Cb + r * (size_t)N + c) = v;
        }
    }
}

// ---------------------------------------------------------------------------
// Row softmax over S=2048 with diagonal (j == row%S) masked to -inf.
// One block (256 threads) per row; row cached in smem.
// ---------------------------------------------------------------------------
__device__ __forceinline__ float warp_max(float v) {
    #pragma unroll
    for (int o = 16; o > 0; o >>= 1) v = fmaxf(v, __shfl_xor_sync(0xffffffffu, v, o));
    return v;
}
__device__ __forceinline__ float warp_sum(float v) {
    #pragma unroll
    for (int o = 16; o > 0; o >>= 1) v += __shfl_xor_sync(0xffffffffu, v, o);
    return v;
}

__global__ __launch_bounds__(256)
void softmax_mask_kernel(float* __restrict__ sm)
{
    const int row  = blockIdx.x;       // 0..B*S-1
    const int diag = row & (S - 1);    // within-batch query index
    float* p = sm + (size_t)row * S;

    __shared__ float buf[S];
    __shared__ float red[8];
    const int tid = threadIdx.x;

    float mx = -CUDART_INF_F;
    for (int j = tid; j < S; j += 256) {
        float v = p[j];
        if (j == diag) v = -CUDART_INF_F;
        buf[j] = v;
        mx = fmaxf(mx, v);
    }
    mx = warp_max(mx);
    if ((tid & 31) == 0) red[tid >> 5] = mx;
    __syncthreads();
    if (tid == 0) {
        float m = red[0];
        #pragma unroll
        for (int w = 1; w < 8; ++w) m = fmaxf(m, red[w]);
        red[0] = m;
    }
    __syncthreads();
    mx = red[0];

    float sum = 0.f;
    for (int j = tid; j < S; j += 256) {
        float e = expf(buf[j] - mx);   // exp(-inf) -> 0 handles the mask
        buf[j] = e;
        sum += e;
    }
    sum = warp_sum(sum);
    __syncthreads();
    if ((tid & 31) == 0) red[tid >> 5] = sum;
    __syncthreads();
    if (tid == 0) {
        float t = 0.f;
        #pragma unroll
        for (int w = 0; w < 8; ++w) t += red[w];
        red[0] = t;
    }
    __syncthreads();
    const float inv = 1.0f / red[0];

    for (int j = tid; j < S; j += 256) p[j] = buf[j] * inv;
}

// ---------------------------------------------------------------------------
// Launch: Wx = x@W^T ; s = Wx@x^T ; softmax(mask) ; c = a@x ;
//         out = x + relu(c@proj_w^T + b)
// ---------------------------------------------------------------------------
extern "C" void kernel_launch(void* const* d_in, const int* in_sizes, int n_in,
                              void* d_out, int out_size)
{
    const float* x  = (const float*)d_in[0];
    const float* W  = (const float*)d_in[1];
    const float* pw = (const float*)d_in[2];
    const float* pb = (const float*)d_in[3];
    float* out = (float*)d_out;

    float *Wx, *sb, *cb;
    cudaGetSymbolAddress((void**)&Wx, g_Wx);
    cudaGetSymbolAddress((void**)&sb, g_s);
    cudaGetSymbolAddress((void**)&cb, g_c);

    const dim3 blk(NTHREADS);

    // GEMM1: Wx[16384,768] = x[16384,768] @ W[768,768]^T
    gemm_nt_kernel<false><<<dim3(D / BN, M_TOT / BM, 1), blk>>>(
        x, W, Wx, M_TOT, D, D, 0, 0, 0, nullptr, nullptr);

    // GEMM2 (batched): s[b][2048,2048] = Wx[b] @ x[b]^T
    gemm_nt_kernel<false><<<dim3(S / BN, S / BM, B), blk>>>(
        Wx, x, sb, S, S, D,
        (size_t)S * D, (size_t)S * D, (size_t)S * S, nullptr, nullptr);

    // Masked softmax over rows of s
    softmax_mask_kernel<<<B * S, 256>>>(sb);

    // GEMM3 (batched, nn): c[b][2048,768] = a[b][2048,2048] @ x[b][2048,768]
    gemm_nn_kernel<<<dim3(D / BN, S / BM, B), blk>>>(
        sb, x, cb, S, D, S,
        (size_t)S * S, (size_t)S * D, (size_t)S * D);

    // GEMM4 + epilogue: out = x + relu(c @ proj_w^T + pb)
    gemm_nt_kernel<true><<<dim3(D / BN, M_TOT / BM, 1), blk>>>(
        cb, pw, out, M_TOT, D, D, 0, 0, 0, pb, x);
}

// round 4
// speedup vs baseline: 3.6349x; 3.6349x over previous
#include <cuda_runtime.h>
#include <cuda_fp16.h>
#include <mma.h>
#include <cstdint>
#include <math_constants.h>

using namespace nvcuda;

static constexpr int B = 8, S = 2048, D = 768;
static constexpr int M_TOT = B * S; // 16384

// ---------------------------------------------------------------------------
// Scratch (__device__ globals — allocation-free rule)
// ---------------------------------------------------------------------------
__device__ __half g_xh [(size_t)B * S * D];
__device__ __half g_xl [(size_t)B * S * D];
__device__ __half g_xTh[(size_t)B * S * D];   // [B, D, S]
__device__ __half g_Wh [D * D];
__device__ __half g_Wl [D * D];
__device__ __half g_pwh[D * D];
__device__ __half g_Wxh[(size_t)B * S * D];
__device__ __half g_Wxl[(size_t)B * S * D];
__device__ __half g_ah [(size_t)B * S * S];   // softmax output fp16
__device__ __half g_ch [(size_t)B * S * D];
__device__ float  g_s  [(size_t)B * S * S];   // logits fp32

// ---------------------------------------------------------------------------
// cp.async helpers
// ---------------------------------------------------------------------------
__device__ __forceinline__ uint32_t smem_u32(const void* p) {
    uint32_t a;
    asm("{ .reg .u64 t; cvta.to.shared.u64 t, %1; cvt.u32.u64 %0, t; }" : "=r"(a) : "l"(p));
    return a;
}
__device__ __forceinline__ void cp16(uint32_t saddr, const void* g) {
    asm volatile("cp.async.cg.shared.global [%0], [%1], 16;" :: "r"(saddr), "l"(g));
}
__device__ __forceinline__ void cp_commit() { asm volatile("cp.async.commit_group;" ::: "memory"); }
__device__ __forceinline__ void cp_wait1()  { asm volatile("cp.async.wait_group 1;" ::: "memory"); }

// ---------------------------------------------------------------------------
// hgemm: C[M,N] = A[M,K] * B[N,K]^T  (both operands K-contiguous fp16)
// Tiles 128x128, BK=64, 256 threads (8 warps, each 64x32 via wmma 16x16x16).
// Smem tiles stored row-major with LDH=72 halves (144B rows — conflict-free).
// SP3: 3-pass compensated product (Ah*Bh + Ah*Bl + Al*Bh).
// EPI: 0 = fp32 C (direct wmma store); 1 = split fp16 (Ch+Cl);
//      2 = fp16 Ch; 3 = fp32 resid + relu(C + bias)
// ---------------------------------------------------------------------------
static constexpr int LDH = 72;                       // halves per smem row
static constexpr uint32_t TILE_B = 128 * LDH * 2;    // 18432 bytes per tile

template <bool SP3>
__device__ __forceinline__ void load_chunk(
    uint32_t sb, const __half* Ah, const __half* Al,
    const __half* Bh, const __half* Bl,
    int lda, int ldb, int rowBase, int colBase, int k0, int tid)
{
    #pragma unroll
    for (int i = 0; i < 4; ++i) {
        const int g = tid + i * 256;          // 1024 granules of 16B per tile
        const int r = g >> 3;                 // 0..127
        const int c = g & 7;                  // 0..7 (8 halves each)
        const uint32_t off = (uint32_t)(r * (LDH * 2) + c * 16);
        const size_t ga = (size_t)(rowBase + r) * lda + k0 + c * 8;
        const size_t gb = (size_t)(colBase + r) * ldb + k0 + c * 8;
        cp16(sb + off, Ah + ga);
        if (SP3) cp16(sb + TILE_B + off, Al + ga);
        cp16(sb + (SP3 ? 2 : 1) * TILE_B + off, Bh + gb);
        if (SP3) cp16(sb + 3 * TILE_B + off, Bl + gb);
    }
}

template <bool SP3>
__device__ __forceinline__ void compute_chunk(
    const __half* sm,
    wmma::fragment<wmma::accumulator, 16, 16, 16, float> acc[4][2],
    int warp_m, int warp_n)
{
    const __half* As = sm;
    const __half* Als = sm + 128 * LDH;                    // only used if SP3
    const __half* Bs = sm + (SP3 ? 2 : 1) * 128 * LDH;
    const __half* Bls = Bs + 128 * LDH;

    #pragma unroll
    for (int kk = 0; kk < 4; ++kk) {
        wmma::fragment<wmma::matrix_b, 16, 16, 16, __half, wmma::col_major> bh[2], bl[2];
        #pragma unroll
        for (int nj = 0; nj < 2; ++nj) {
            wmma::load_matrix_sync(bh[nj], Bs + (size_t)(warp_n + nj * 16) * LDH + kk * 16, LDH);
            if (SP3)
                wmma::load_matrix_sync(bl[nj], Bls + (size_t)(warp_n + nj * 16) * LDH + kk * 16, LDH);
        }
        #pragma unroll
        for (int mi = 0; mi < 4; ++mi) {
            wmma::fragment<wmma::matrix_a, 16, 16, 16, __half, wmma::row_major> a;
            wmma::load_matrix_sync(a, As + (size_t)(warp_m + mi * 16) * LDH + kk * 16, LDH);
            #pragma unroll
            for (int nj = 0; nj < 2; ++nj)
                wmma::mma_sync(acc[mi][nj], a, bh[nj], acc[mi][nj]);
            if (SP3) {
                #pragma unroll
                for (int nj = 0; nj < 2; ++nj)
                    wmma::mma_sync(acc[mi][nj], a, bl[nj], acc[mi][nj]);
                wmma::fragment<wmma::matrix_a, 16, 16, 16, __half, wmma::row_major> al;
                wmma::load_matrix_sync(al, Als + (size_t)(warp_m + mi * 16) * LDH + kk * 16, LDH);
                #pragma unroll
                for (int nj = 0; nj < 2; ++nj)
                    wmma::mma_sync(acc[mi][nj], al, bh[nj], acc[mi][nj]);
            }
        }
    }
}

template <bool SP3, int EPI>
__global__ __launch_bounds__(256)
void hgemm(const __half* __restrict__ Ah, const __half* __restrict__ Al,
           const __half* __restrict__ Bh, const __half* __restrict__ Bl,
           float* __restrict__ Cf, __half* __restrict__ Ch, __half* __restrict__ Cl,
           const float* __restrict__ bias, const float* __restrict__ resid,
           int lda, int ldb, int ldc, int K,
           size_t sA, size_t sB, size_t sC)
{
    extern __shared__ char smem[];
    const uint32_t sb0 = smem_u32(smem);
    constexpr uint32_t BUF = TILE_B * (SP3 ? 4 : 2);

    const int tid = threadIdx.x, wid = tid >> 5;
    const int rowBase = blockIdx.y * 128;
    const int colBase = blockIdx.x * 128;
    const int warp_m = (wid >> 2) * 64;   // 0 or 64
    const int warp_n = (wid & 3) * 32;    // 0,32,64,96

    Ah += (size_t)blockIdx.z * sA;
    Bh += (size_t)blockIdx.z * sB;
    if (SP3) { Al += (size_t)blockIdx.z * sA; Bl += (size_t)blockIdx.z * sB; }

    wmma::fragment<wmma::accumulator, 16, 16, 16, float> acc[4][2];
    #pragma unroll
    for (int mi = 0; mi < 4; ++mi)
        #pragma unroll
        for (int nj = 0; nj < 2; ++nj)
            wmma::fill_fragment(acc[mi][nj], 0.0f);

    const int NK = K >> 6;

    load_chunk<SP3>(sb0, Ah, Al, Bh, Bl, lda, ldb, rowBase, colBase, 0, tid);
    cp_commit();

    for (int ck = 0; ck < NK; ++ck) {
        if (ck + 1 < NK)
            load_chunk<SP3>(sb0 + ((ck + 1) & 1) * BUF, Ah, Al, Bh, Bl,
                            lda, ldb, rowBase, colBase, (ck + 1) << 6, tid);
        cp_commit();
        cp_wait1();
        __syncthreads();
        compute_chunk<SP3>((const __half*)(smem + (ck & 1) * BUF), acc, warp_m, warp_n);
        __syncthreads();
    }

    if (EPI == 0) {
        // direct fp32 store (GEMM2 path — the big output)
        #pragma unroll
        for (int mi = 0; mi < 4; ++mi)
            #pragma unroll
            for (int nj = 0; nj < 2; ++nj) {
                float* dst = (Cf + (size_t)blockIdx.z * sC)
                           + (size_t)(rowBase + warp_m + mi * 16) * ldc
                           + colBase + warp_n + nj * 16;
                wmma::store_matrix_sync(dst, acc[mi][nj], ldc, wmma::mem_row_major);
            }
        return;
    }

    // staged epilogue: park the 128x128 fp32 tile in smem, then transform.
    float* stg = (float*)smem;
    #pragma unroll
    for (int mi = 0; mi < 4; ++mi)
        #pragma unroll
        for (int nj = 0; nj < 2; ++nj)
            wmma::store_matrix_sync(stg + (size_t)(warp_m + mi * 16) * 128 + warp_n + nj * 16,
                                    acc[mi][nj], 128, wmma::mem_row_major);
    __syncthreads();

    #pragma unroll
    for (int i = 0; i < 16; ++i) {
        const int idx = i * 256 + tid;   // 4096 float4 chunks
        const int el = idx * 4;
        const int row = el >> 7;
        const int col = el & 127;
        const float4 v = *(const float4*)(stg + el);
        const size_t m = (size_t)(rowBase + row);
        const int n = colBase + col;
        if (EPI == 1) {
            __half* ChB = Ch + (size_t)blockIdx.z * sC;
            __half* ClB = Cl + (size_t)blockIdx.z * sC;
            const __half h0 = __float2half_rn(v.x), h1 = __float2half_rn(v.y);
            const __half h2 = __float2half_rn(v.z), h3 = __float2half_rn(v.w);
            *(__half2*)(ChB + m * ldc + n)     = __halves2half2(h0, h1);
            *(__half2*)(ChB + m * ldc + n + 2) = __halves2half2(h2, h3);
            *(__half2*)(ClB + m * ldc + n) =
                __halves2half2(__float2half_rn(v.x - __half2float(h0)),
                               __float2half_rn(v.y - __half2float(h1)));
            *(__half2*)(ClB + m * ldc + n + 2) =
                __halves2half2(__float2half_rn(v.z - __half2float(h2)),
                               __float2half_rn(v.w - __half2float(h3)));
        } else if (EPI == 2) {
            __half* ChB = Ch + (size_t)blockIdx.z * sC;
            *(__half2*)(ChB + m * ldc + n)     = __halves2half2(__float2half_rn(v.x), __float2half_rn(v.y));
            *(__half2*)(ChB + m * ldc + n + 2) = __halves2half2(__float2half_rn(v.z), __float2half_rn(v.w));
        } else { // EPI == 3
            const float4 bb = *(const float4*)(bias + n);
            const float4 rr = *(const float4*)(resid + m * ldc + n);
            float4 o;
            o.x = fmaxf(v.x + bb.x, 0.f) + rr.x;
            o.y = fmaxf(v.y + bb.y, 0.f) + rr.y;
            o.z = fmaxf(v.z + bb.z, 0.f) + rr.z;
            o.w = fmaxf(v.w + bb.w, 0.f) + rr.w;
            *(float4*)(Cf + m * ldc + n) = o;
        }
    }
}

// ---------------------------------------------------------------------------
// Prep kernels
// ---------------------------------------------------------------------------
__global__ __launch_bounds__(256)
void prep_x_kernel(const float* __restrict__ x, __half* __restrict__ xh, __half* __restrict__ xl)
{
    const size_t i = (size_t)blockIdx.x * 256 + threadIdx.x;
    const size_t n = (size_t)B * S * D;
    if (i < n) {
        const float v = x[i];
        const __half h = __float2half_rn(v);
        xh[i] = h;
        xl[i] = __float2half_rn(v - __half2float(h));
    }
}

__global__ __launch_bounds__(256)
void prep_w_kernel(const float* __restrict__ W, const float* __restrict__ pw,
                   __half* __restrict__ Wh, __half* __restrict__ Wl, __half* __restrict__ pwh)
{
    const int i = blockIdx.x * 256 + threadIdx.x;
    if (i < D * D) {
        const float v = W[i];
        const __half h = __float2half_rn(v);
        Wh[i] = h;
        Wl[i] = __float2half_rn(v - __half2float(h));
        pwh[i] = __float2half_rn(pw[i]);
    }
}

// x [B,S,D] fp32 -> xTh [B,D,S] fp16
__global__ __launch_bounds__(256)
void transpose_half_kernel(const float* __restrict__ x, __half* __restrict__ xT)
{
    __shared__ float tile[32][33];
    const int b = blockIdx.z;
    const int s0 = blockIdx.x * 32;
    const int d0 = blockIdx.y * 32;
    const float* xb = x + (size_t)b * S * D;
    __half* xtb = xT + (size_t)b * S * D;
    const int tx = threadIdx.x & 31, ty = threadIdx.x >> 5;
    #pragma unroll
    for (int i = 0; i < 32; i += 8)
        tile[ty + i][tx] = xb[(size_t)(s0 + ty + i) * D + d0 + tx];
    __syncthreads();
    #pragma unroll
    for (int i = 0; i < 32; i += 8)
        xtb[(size_t)(d0 + ty + i) * S + s0 + tx] = __float2half_rn(tile[tx][ty + i]);
}

// ---------------------------------------------------------------------------
// Masked softmax: rows of s [B*S, S] fp32 -> a fp16 (diag masked)
// ---------------------------------------------------------------------------
__device__ __forceinline__ float warp_max(float v) {
    #pragma unroll
    for (int o = 16; o > 0; o >>= 1) v = fmaxf(v, __shfl_xor_sync(0xffffffffu, v, o));
    return v;
}
__device__ __forceinline__ float warp_sum(float v) {
    #pragma unroll
    for (int o = 16; o > 0; o >>= 1) v += __shfl_xor_sync(0xffffffffu, v, o);
    return v;
}

__global__ __launch_bounds__(256)
void softmax_mask_kernel(const float* __restrict__ s, __half* __restrict__ a)
{
    const int row  = blockIdx.x;
    const int diag = row & (S - 1);
    const float* p = s + (size_t)row * S;
    __half* q = a + (size_t)row * S;

    __shared__ float buf[S];
    __shared__ float red[8];
    const int tid = threadIdx.x;

    float mx = -CUDART_INF_F;
    for (int j = tid; j < S; j += 256) {
        float v = p[j];
        if (j == diag) v = -CUDART_INF_F;
        buf[j] = v;
        mx = fmaxf(mx, v);
    }
    mx = warp_max(mx);
    if ((tid & 31) == 0) red[tid >> 5] = mx;
    __syncthreads();
    if (tid == 0) {
        float m = red[0];
        #pragma unroll
        for (int w = 1; w < 8; ++w) m = fmaxf(m, red[w]);
        red[0] = m;
    }
    __syncthreads();
    mx = red[0];

    float sum = 0.f;
    for (int j = tid; j < S; j += 256) {
        const float e = expf(buf[j] - mx);
        buf[j] = e;
        sum += e;
    }
    sum = warp_sum(sum);
    __syncthreads();
    if ((tid & 31) == 0) red[tid >> 5] = sum;
    __syncthreads();
    if (tid == 0) {
        float t = 0.f;
        #pragma unroll
        for (int w = 0; w < 8; ++w) t += red[w];
        red[0] = t;
    }
    __syncthreads();
    const float inv = 1.0f / red[0];
    for (int j = tid; j < S; j += 256) q[j] = __float2half_rn(buf[j] * inv);
}

// ---------------------------------------------------------------------------
// Launch
// ---------------------------------------------------------------------------
extern "C" void kernel_launch(void* const* d_in, const int* in_sizes, int n_in,
                              void* d_out, int out_size)
{
    const float* x  = (const float*)d_in[0];
    const float* W  = (const float*)d_in[1];
    const float* pw = (const float*)d_in[2];
    const float* pb = (const float*)d_in[3];
    float* out = (float*)d_out;

    __half *xh, *xl, *xTh, *Wh, *Wl, *pwh, *Wxh, *Wxl, *ah, *ch;
    float *sbuf;
    cudaGetSymbolAddress((void**)&xh,  g_xh);
    cudaGetSymbolAddress((void**)&xl,  g_xl);
    cudaGetSymbolAddress((void**)&xTh, g_xTh);
    cudaGetSymbolAddress((void**)&Wh,  g_Wh);
    cudaGetSymbolAddress((void**)&Wl,  g_Wl);
    cudaGetSymbolAddress((void**)&pwh, g_pwh);
    cudaGetSymbolAddress((void**)&Wxh, g_Wxh);
    cudaGetSymbolAddress((void**)&Wxl, g_Wxl);
    cudaGetSymbolAddress((void**)&ah,  g_ah);
    cudaGetSymbolAddress((void**)&ch,  g_ch);
    cudaGetSymbolAddress((void**)&sbuf, g_s);

    // smem: double-buffered tiles; staged epilogues need >= 64KB for the fp32 tile
    constexpr int SMEM_SP3   = (int)(2 * TILE_B * 4); // 147456
    constexpr int SMEM_PLAIN = (int)(2 * TILE_B * 2); //  73728
    cudaFuncSetAttribute(hgemm<true, 1>,  cudaFuncAttributeMaxDynamicSharedMemorySize, SMEM_SP3);
    cudaFuncSetAttribute(hgemm<true, 0>,  cudaFuncAttributeMaxDynamicSharedMemorySize, SMEM_SP3);
    cudaFuncSetAttribute(hgemm<false, 2>, cudaFuncAttributeMaxDynamicSharedMemorySize, SMEM_PLAIN);
    cudaFuncSetAttribute(hgemm<false, 3>, cudaFuncAttributeMaxDynamicSharedMemorySize, SMEM_PLAIN);

    const size_t SD = (size_t)S * D, SS = (size_t)S * S;

    // prep
    prep_x_kernel<<<(unsigned)(((size_t)B * S * D + 255) / 256), 256>>>(x, xh, xl);
    prep_w_kernel<<<(D * D + 255) / 256, 256>>>(W, pw, Wh, Wl, pwh);
    transpose_half_kernel<<<dim3(S / 32, D / 32, B), 256>>>(x, xTh);

    // GEMM1 (fp16x3): Wx = x @ W^T  -> split fp16 (Wxh, Wxl)
    hgemm<true, 1><<<dim3(D / 128, M_TOT / 128, 1), 256, SMEM_SP3>>>(
        xh, xl, Wh, Wl, nullptr, Wxh, Wxl, nullptr, nullptr,
        D, D, D, D, 0, 0, 0);

    // GEMM2 (fp16x3, batched): s[b] = Wx[b] @ x[b]^T -> fp32
    hgemm<true, 0><<<dim3(S / 128, S / 128, B), 256, SMEM_SP3>>>(
        Wxh, Wxl, xh, xl, sbuf, nullptr, nullptr, nullptr, nullptr,
        D, D, S, D, SD, SD, SS);

    // masked softmax -> fp16 a
    softmax_mask_kernel<<<B * S, 256>>>(sbuf, ah);

    // GEMM3 (fp16, batched): c[b] = a[b] @ x[b] -> fp16 ch   (B operand = xT)
    hgemm<false, 2><<<dim3(D / 128, S / 128, B), 256, SMEM_PLAIN>>>(
        ah, nullptr, xTh, nullptr, nullptr, ch, nullptr, nullptr, nullptr,
        S, S, D, S, SS, SD, SD);

    // GEMM4 (fp16 + epilogue): out = x + relu(c @ pw^T + pb)
    hgemm<false, 3><<<dim3(D / 128, M_TOT / 128, 1), 256, SMEM_PLAIN>>>(
        ch, nullptr, pwh, nullptr, out, nullptr, nullptr, pb, x,
        D, D, D, D, 0, 0, 0);
}